// round 15
// baseline (speedup 1.0000x reference)
#include <cuda_runtime.h>
#include <cuda_fp16.h>
#include <cstdint>

// Problem constants
#define NH   8
#define DM   512
#define FFD  2048
#define BB   8
#define TT   512
#define SS   1024
#define LAYER 5

// ---------------- scratch (device globals) ------------------------------------
__device__ __half g_nh  [BB*TT*DM];
__device__ __half g_qh  [BB*TT*DM];
__device__ __half g_qkvh[BB*TT*3*DM];
__device__ __half g_kvh [BB*SS*2*DM];
__device__ __half g_vth [DM*BB*TT];
__device__ __half g_vth2[DM*BB*SS];
__device__ __half g_ath [BB*TT*DM];
__device__ __half g_ffh [BB*TT*FFD];
__device__ __half g_memh[BB*SS*DM];
__device__ __half g_wth [8*DM*DM];
__device__ __half g_w1th[FFD*DM];
__device__ __half g_w2th[DM*FFD];
__device__ float  g_x   [BB*TT*DM];
__device__ float  g_bc1 [3*DM];
__device__ float  g_bc2 [2*DM];

// ---------------- helpers ------------------------------------------------------
__device__ __forceinline__ uint32_t smem_u32(const void* p) {
    uint32_t a;
    asm("{ .reg .u64 t; cvta.to.shared.u64 t, %1; cvt.u32.u64 %0, t; }" : "=r"(a) : "l"(p));
    return a;
}
__device__ __forceinline__ uint32_t h2u(__half2 h) { return *(uint32_t*)&h; }

#define CP16(dst, src) \
    asm volatile("cp.async.cg.shared.global [%0], [%1], 16;" :: "r"(dst), "l"(src))
#define CP_COMMIT() asm volatile("cp.async.commit_group;" ::: "memory")
#define CP_WAIT1()  asm volatile("cp.async.wait_group 1;" ::: "memory")
#define CP_WAIT0()  asm volatile("cp.async.wait_group 0;" ::: "memory")

#define MMA_F16(c, a, b) \
    asm volatile("mma.sync.aligned.m16n8k16.row.col.f32.f16.f16.f32 " \
        "{%0,%1,%2,%3}, {%4,%5,%6,%7}, {%8,%9}, {%0,%1,%2,%3};" \
        : "+f"((c)[0]), "+f"((c)[1]), "+f"((c)[2]), "+f"((c)[3]) \
        : "r"((a)[0]), "r"((a)[1]), "r"((a)[2]), "r"((a)[3]), "r"((b)[0]), "r"((b)[1]))

#define LDSM4(d0, d1, d2, d3, addr) \
    asm volatile("ldmatrix.sync.aligned.m8n8.x4.shared.b16 {%0,%1,%2,%3}, [%4];" \
        : "=r"(d0), "=r"(d1), "=r"(d2), "=r"(d3) : "r"(addr))

// ============ mma.sync fp16 GEMM, 3-stage pipeline, ldmatrix fragments =========
template<int BN, int EPI, int HOUT, int VT>
__global__ __launch_bounds__(256) void mma_gemm(
    const __half* __restrict__ A, int lda,
    const __half* __restrict__ B, int ldb,
    const float* __restrict__ bias, const float* __restrict__ res,
    void* __restrict__ Cv, int ldc, int K,
    __half* __restrict__ vtp, int vtn0, int vtld)
{
    constexpr int WTM = (BN == 128) ? 64 : 32;
    constexpr int MW  = 128 / WTM;
    constexpr int MF  = WTM / 16;
    constexpr int NF  = 4;
    constexpr int SSZB = (128 + BN) * 128;

    const int m0 = blockIdx.y * 128;
    const int n0 = blockIdx.x * BN;

    extern __shared__ char smem[];
    const uint32_t uS = smem_u32(smem);

    const int tid  = threadIdx.x;
    const int lane = tid & 31;
    const int wid  = tid >> 5;
    const int wm   = wid & (MW - 1);
    const int wn   = wid / MW;
    const int laneR = lane >> 2, laneC = lane & 3;

    const int mat = lane >> 3, mrr = lane & 7;
    const int ag_hi = mat >> 1;
    const int bg_lo = mat & 1;
    int aro[MF], arx[MF];
#pragma unroll
    for (int mf = 0; mf < MF; mf++) {
        int r = wm * WTM + mf * 16 + ((mat & 1) << 3) + mrr;
        aro[mf] = r * 128; arx[mf] = r & 7;
    }
    int bro[NF / 2], brx[NF / 2];
#pragma unroll
    for (int p = 0; p < NF / 2; p++) {
        int r = wn * 32 + (2 * p + (mat >> 1)) * 8 + mrr;
        bro[p] = r * 128; brx[p] = r & 7;
    }

    const int nch = K >> 6;

    auto load_chunk = [&](int c) {
        const int st = c % 3;
        const uint32_t ua = uS + st * SSZB;
        const uint32_t ub = ua + 128 * 128;
        const int k0 = c << 6;
#pragma unroll
        for (int i = 0; i < 4; i++) {
            int idx = tid + i * 256; int r = idx >> 3, f = idx & 7;
            CP16(ua + r * 128 + ((f ^ (r & 7)) << 4),
                 A + (size_t)(m0 + r) * lda + k0 + f * 8);
        }
#pragma unroll
        for (int i = 0; i < BN / 32; i++) {
            int idx = tid + i * 256; int r = idx >> 3, f = idx & 7;
            CP16(ub + r * 128 + ((f ^ (r & 7)) << 4),
                 B + (size_t)(n0 + r) * ldb + k0 + f * 8);
        }
        CP_COMMIT();
    };

    float acc[MF][NF][4] = {};

    load_chunk(0);
    load_chunk(1);
    for (int c = 0; c < nch; c++) {
        if (c + 1 < nch) CP_WAIT1(); else CP_WAIT0();
        __syncthreads();
        if (c + 2 < nch) load_chunk(c + 2);
        const int st = c % 3;
        const uint32_t uA_s = uS + st * SSZB;
        const uint32_t uB_s = uA_s + 128 * 128;
#pragma unroll
        for (int ks = 0; ks < 4; ks++) {
            const int gA = 2 * ks + ag_hi;
            const int gB = 2 * ks + bg_lo;
            uint32_t af[MF][4];
#pragma unroll
            for (int mf = 0; mf < MF; mf++)
                LDSM4(af[mf][0], af[mf][1], af[mf][2], af[mf][3],
                      uA_s + aro[mf] + ((gA ^ arx[mf]) << 4));
            uint32_t bf[NF][2];
#pragma unroll
            for (int p = 0; p < NF / 2; p++)
                LDSM4(bf[2*p][0], bf[2*p][1], bf[2*p+1][0], bf[2*p+1][1],
                      uB_s + bro[p] + ((gB ^ brx[p]) << 4));
#pragma unroll
            for (int mf = 0; mf < MF; mf++)
#pragma unroll
                for (int nf = 0; nf < NF; nf++)
                    MMA_F16(acc[mf][nf], af[mf], bf[nf]);
        }
    }

    const bool isv = VT && (n0 >= vtn0);
#pragma unroll
    for (int mf = 0; mf < MF; mf++) {
#pragma unroll
        for (int nf = 0; nf < NF; nf++) {
            int r  = m0 + wm * WTM + mf * 16 + laneR;
            int cc = n0 + wn * 32 + nf * 8 + laneC * 2;
            float v0 = acc[mf][nf][0], v1 = acc[mf][nf][1];
            float v2 = acc[mf][nf][2], v3 = acc[mf][nf][3];
            float2 bb = *(const float2*)(bias + cc);
            v0 += bb.x; v1 += bb.y; v2 += bb.x; v3 += bb.y;
            if (EPI == 1) {
                v0 = fmaxf(v0, 0.f); v1 = fmaxf(v1, 0.f);
                v2 = fmaxf(v2, 0.f); v3 = fmaxf(v3, 0.f);
            }
            if (EPI == 2) {
                float2 r0 = *(const float2*)(res + (size_t)r * ldc + cc);
                float2 r1 = *(const float2*)(res + (size_t)(r + 8) * ldc + cc);
                v0 += r0.x; v1 += r0.y; v2 += r1.x; v3 += r1.y;
            }
            if (isv) {
                __half* c0 = vtp + (size_t)(cc     - vtn0) * vtld;
                __half* c1 = vtp + (size_t)(cc + 1 - vtn0) * vtld;
                c0[r] = __float2half(v0); c1[r] = __float2half(v1);
                c0[r + 8] = __float2half(v2); c1[r + 8] = __float2half(v3);
            } else if (HOUT) {
                __half* Ch = (__half*)Cv;
                *(__half2*)(Ch + (size_t)r * ldc + cc)       = __floats2half2_rn(v0, v1);
                *(__half2*)(Ch + (size_t)(r + 8) * ldc + cc) = __floats2half2_rn(v2, v3);
            } else {
                float* Cf = (float*)Cv;
                *(float2*)(Cf + (size_t)r * ldc + cc)       = make_float2(v0, v1);
                *(float2*)(Cf + (size_t)(r + 8) * ldc + cc) = make_float2(v2, v3);
            }
        }
    }
}

// ============ fused flash attention (fp16, 3-stage KV ring, P in registers) ====
template<int CAUSAL, int NW>
__global__ __launch_bounds__(NW * 32, 16 / NW) void flash_attn(
    const __half* __restrict__ Q, int ldq,
    const __half* __restrict__ Kg, int ldk,
    const __half* __restrict__ Vt, __half* __restrict__ O, int Slen)
{
    constexpr int NT = NW * 32;
    constexpr int MT = NW * 16;
    extern __shared__ char sm[];
    const uint32_t uQ = smem_u32(sm);
    const uint32_t uK = uQ + MT * 128;
    const uint32_t uV = uK + 24576;

    const int mt = blockIdx.x, bh = blockIdx.y;
    const int b = bh >> 3, h = bh & 7;
    const int m0 = mt * MT;
    const int tid = threadIdx.x, lane = tid & 31, wid = tid >> 5;
    const int laneR = lane >> 2, laneC = lane & 3;

    const __half* Qp = Q + ((size_t)b * TT + m0) * ldq + h * 64;
    const __half* Kp = Kg + (size_t)b * Slen * ldk + h * 64;
    const __half* Vp = Vt + (size_t)(h * 64) * (BB * Slen) + (size_t)b * Slen;
    __half* Op = O + ((size_t)b * TT + m0) * DM + h * 64;

    const int wr0 = wid * 16;

    const int mat = lane >> 3, mrr = lane & 7;
    const int ag_hi = mat >> 1;
    const int bg_lo = mat & 1;
    const int qrow = wr0 + ((mat & 1) << 3) + mrr;
    const int qro = qrow * 128, qrx = qrow & 7;
    int bro[4], brx[4];
#pragma unroll
    for (int p = 0; p < 4; p++) {
        int r = p * 16 + ((mat >> 1) << 3) + mrr;
        bro[p] = r * 128; brx[p] = r & 7;
    }

#pragma unroll
    for (int i = 0; i < 4; i++) {
        int idx = tid + i * NT;
        int r = idx >> 3, f = idx & 7;
        CP16(uQ + r * 128 + ((f ^ (r & 7)) << 4), Qp + (size_t)r * ldq + f * 8);
    }

    auto load_kv = [&](int c) {
        const int st = c % 3;
        const int s0 = c * 64;
#pragma unroll
        for (int i = 0; i < 16 / NW; i++) {
            int idx = tid + i * NT;
            int r = idx >> 3, f = idx & 7;
            CP16(uK + st * 8192 + r * 128 + ((f ^ (r & 7)) << 4),
                 Kp + (size_t)(s0 + r) * ldk + f * 8);
        }
#pragma unroll
        for (int i = 0; i < 16 / NW; i++) {
            int idx = tid + i * NT;
            int r = idx >> 3, f = idx & 7;
            CP16(uV + st * 8192 + r * 128 + ((f ^ (r & 7)) << 4),
                 Vp + (size_t)r * (BB * Slen) + s0 + f * 8);
        }
        CP_COMMIT();
    };

    const int nch = CAUSAL ? (m0 + MT) / 64 : Slen / 64;
    float mr0 = -1e30f, mr1 = -1e30f, l0 = 0.f, l1 = 0.f;
    float oacc[8][4] = {};

    load_kv(0);
    load_kv(1);
    for (int c = 0; c < nch; c++) {
        if (c + 1 < nch) CP_WAIT1(); else CP_WAIT0();
        __syncthreads();
        if (c + 2 < nch) load_kv(c + 2);
        const int s0 = c * 64;
        const bool active = !CAUSAL || (s0 <= m0 + wr0 + 15);
        if (active) {
            const uint32_t uKb = uK + (c % 3) * 8192;
            const uint32_t uVb = uV + (c % 3) * 8192;

            float sacc[8][4] = {};
#pragma unroll
            for (int ks = 0; ks < 4; ks++) {
                const int gA = 2 * ks + ag_hi;
                const int gB = 2 * ks + bg_lo;
                uint32_t af[4];
                LDSM4(af[0], af[1], af[2], af[3], uQ + qro + ((gA ^ qrx) << 4));
                uint32_t bf[8][2];
#pragma unroll
                for (int p = 0; p < 4; p++)
                    LDSM4(bf[2*p][0], bf[2*p][1], bf[2*p+1][0], bf[2*p+1][1],
                          uKb + bro[p] + ((gB ^ brx[p]) << 4));
#pragma unroll
                for (int nf = 0; nf < 8; nf++)
                    MMA_F16(sacc[nf], af, bf[nf]);
            }

            const float SCL = 0.125f;
            const int t0g = m0 + wr0 + laneR;
            float rmax0 = -1e30f, rmax1 = -1e30f;
#pragma unroll
            for (int nf = 0; nf < 8; nf++) {
                int sg = s0 + nf * 8 + 2 * laneC;
                float v0 = sacc[nf][0] * SCL, v1 = sacc[nf][1] * SCL;
                float v2 = sacc[nf][2] * SCL, v3 = sacc[nf][3] * SCL;
                if (CAUSAL) {
                    if (sg     > t0g)     v0 = -1e30f;
                    if (sg + 1 > t0g)     v1 = -1e30f;
                    if (sg     > t0g + 8) v2 = -1e30f;
                    if (sg + 1 > t0g + 8) v3 = -1e30f;
                }
                sacc[nf][0] = v0; sacc[nf][1] = v1;
                sacc[nf][2] = v2; sacc[nf][3] = v3;
                rmax0 = fmaxf(rmax0, fmaxf(v0, v1));
                rmax1 = fmaxf(rmax1, fmaxf(v2, v3));
            }
            rmax0 = fmaxf(rmax0, __shfl_xor_sync(0xffffffffu, rmax0, 1));
            rmax0 = fmaxf(rmax0, __shfl_xor_sync(0xffffffffu, rmax0, 2));
            rmax1 = fmaxf(rmax1, __shfl_xor_sync(0xffffffffu, rmax1, 1));
            rmax1 = fmaxf(rmax1, __shfl_xor_sync(0xffffffffu, rmax1, 2));
            float mn0 = fmaxf(mr0, rmax0), mn1 = fmaxf(mr1, rmax1);
            float al0 = __expf(mr0 - mn0), al1 = __expf(mr1 - mn1);
            mr0 = mn0; mr1 = mn1;

            uint32_t ph[8][2];
            float rs0 = 0.f, rs1 = 0.f;
#pragma unroll
            for (int nf = 0; nf < 8; nf++) {
                float e0 = __expf(sacc[nf][0] - mn0);
                float e1 = __expf(sacc[nf][1] - mn0);
                float e2 = __expf(sacc[nf][2] - mn1);
                float e3 = __expf(sacc[nf][3] - mn1);
                rs0 += e0 + e1; rs1 += e2 + e3;
                ph[nf][0] = h2u(__floats2half2_rn(e0, e1));
                ph[nf][1] = h2u(__floats2half2_rn(e2, e3));
            }
            rs0 += __shfl_xor_sync(0xffffffffu, rs0, 1);
            rs0 += __shfl_xor_sync(0xffffffffu, rs0, 2);
            rs1 += __shfl_xor_sync(0xffffffffu, rs1, 1);
            rs1 += __shfl_xor_sync(0xffffffffu, rs1, 2);
            l0 = l0 * al0 + rs0;
            l1 = l1 * al1 + rs1;
#pragma unroll
            for (int nf = 0; nf < 8; nf++) {
                oacc[nf][0] *= al0; oacc[nf][1] *= al0;
                oacc[nf][2] *= al1; oacc[nf][3] *= al1;
            }

#pragma unroll
            for (int j = 0; j < 4; j++) {
                const int gB = 2 * j + bg_lo;
                uint32_t af[4] = { ph[2*j][0], ph[2*j][1], ph[2*j+1][0], ph[2*j+1][1] };
#pragma unroll
                for (int p = 0; p < 4; p++) {
                    uint32_t bf0[2], bf1[2];
                    LDSM4(bf0[0], bf0[1], bf1[0], bf1[1],
                          uVb + bro[p] + ((gB ^ brx[p]) << 4));
                    MMA_F16(oacc[2*p],     af, bf0);
                    MMA_F16(oacc[2*p + 1], af, bf1);
                }
            }
        }
    }

    const float inv0 = 1.f / l0, inv1 = 1.f / l1;
#pragma unroll
    for (int nf = 0; nf < 8; nf++) {
        int cc = nf * 8 + 2 * laneC;
        int r = wr0 + laneR;
        *(__half2*)(Op + (size_t)r * DM + cc) =
            __floats2half2_rn(oacc[nf][0] * inv0, oacc[nf][1] * inv0);
        *(__half2*)(Op + (size_t)(r + 8) * DM + cc) =
            __floats2half2_rn(oacc[nf][2] * inv1, oacc[nf][3] * inv1);
    }
}

// ---------------- prep kernels --------------------------------------------------
struct PrepArgs {
    const float* s8[8]; __half* d8[8];
    const float* w1; __half* w1t;
    const float* w2; __half* w2t;
    const float* bq; const float* bk; const float* bv;
    const float* cbk; const float* cbv;
    float* b1; float* b2;
    const float* mem; __half* memh;
};

__device__ __forceinline__ void tp_tile(
    const float* src, __half* dst, int R, int C, int bx, int by, int tx, int ty)
{
    __shared__ float t[32][33];
    int x = bx * 32 + tx, y = by * 32;
#pragma unroll
    for (int i = 0; i < 4; i++)
        t[ty + i * 8][tx] = src[(size_t)(y + ty + i * 8) * C + x];
    __syncthreads();
    int x2 = by * 32 + tx, y2 = bx * 32;
#pragma unroll
    for (int i = 0; i < 4; i++)
        dst[(size_t)(y2 + ty + i * 8) * R + x2] = __float2half(t[tx][ty + i * 8]);
}

// SA-critical prep: transpose sa wq/wk/wv + bc1 concat. 769 blocks (~2-3 us).
__global__ __launch_bounds__(256) void prep_sa(PrepArgs p)
{
    const int idx = blockIdx.x;
    const int tx = threadIdx.x, ty = threadIdx.y;
    if (idx < 768) {
        int m = idx >> 8, tt = idx & 255;
        tp_tile(p.s8[m], p.d8[m], 512, 512, tt & 15, tt >> 4, tx, ty);
    } else {
        int i = ty * 32 + tx;
#pragma unroll
        for (int j = 0; j < 2; j++) {
            int c = i + j * 256;
            p.b1[c] = p.bq[c]; p.b1[512 + c] = p.bk[c]; p.b1[1024 + c] = p.bv[c];
        }
    }
}

// Rest: slots 3..7, w1, w2, bc2, memory convert.
__global__ __launch_bounds__(256) void prep_rest(PrepArgs p)
{
    const int idx = blockIdx.x;
    const int tx = threadIdx.x, ty = threadIdx.y;
    if (idx < 1280) {
        int m = 3 + (idx >> 8), tt = idx & 255;
        tp_tile(p.s8[m], p.d8[m], 512, 512, tt & 15, tt >> 4, tx, ty);
    } else if (idx < 2304) {
        int tt = idx - 1280;
        tp_tile(p.w1, p.w1t, 512, 2048, tt & 63, tt >> 6, tx, ty);
    } else if (idx < 3328) {
        int tt = idx - 2304;
        tp_tile(p.w2, p.w2t, 2048, 512, tt & 15, tt >> 4, tx, ty);
    } else if (idx == 3328) {
        int i = ty * 32 + tx;
#pragma unroll
        for (int j = 0; j < 2; j++) {
            int c = i + j * 256;
            p.b2[c] = p.cbk[c]; p.b2[512 + c] = p.cbv[c];
        }
    } else {
        int j = idx - 3329;
        int base = j * 2048 + (ty * 32 + tx) * 8;
        float4 a = *(const float4*)(p.mem + base);
        float4 b = *(const float4*)(p.mem + base + 4);
        __half2 h0 = __floats2half2_rn(a.x, a.y);
        __half2 h1 = __floats2half2_rn(a.z, a.w);
        __half2 h2 = __floats2half2_rn(b.x, b.y);
        __half2 h3 = __floats2half2_rn(b.z, b.w);
        uint4 o;
        o.x = *(uint32_t*)&h0; o.y = *(uint32_t*)&h1;
        o.z = *(uint32_t*)&h2; o.w = *(uint32_t*)&h3;
        *(uint4*)(p.memh + base) = o;
    }
}

// ---------------- LayerNorm (float4 in; half or float out) ---------------------
template<int HOUT>
__global__ __launch_bounds__(128) void ln_kernel(
    const float* __restrict__ x, const float* __restrict__ g,
    const float* __restrict__ b, void* __restrict__ outv)
{
    const int row = blockIdx.x;
    const int tid = threadIdx.x;
    float4 v = *(const float4*)(x + (size_t)row * DM + tid * 4);

    float s  = v.x + v.y + v.z + v.w;
    float s2 = v.x * v.x + v.y * v.y + v.z * v.z + v.w * v.w;
#pragma unroll
    for (int o = 16; o; o >>= 1) {
        s  += __shfl_down_sync(0xffffffffu, s,  o);
        s2 += __shfl_down_sync(0xffffffffu, s2, o);
    }
    __shared__ float rs[4], rs2[4];
    int wid = tid >> 5, lane = tid & 31;
    if (lane == 0) { rs[wid] = s; rs2[wid] = s2; }
    __syncthreads();
    if (tid == 0) {
        float a = rs[0] + rs[1] + rs[2] + rs[3];
        float a2 = rs2[0] + rs2[1] + rs2[2] + rs2[3];
        rs[0] = a; rs2[0] = a2;
    }
    __syncthreads();
    float mean = rs[0] * (1.0f / DM);
    float var  = rs2[0] * (1.0f / DM) - mean * mean;
    float inv  = rsqrtf(var + 1e-5f);

    float4 gg = *(const float4*)(g + tid * 4);
    float4 bb = *(const float4*)(b + tid * 4);
    float o0 = (v.x - mean) * inv * gg.x + bb.x;
    float o1 = (v.y - mean) * inv * gg.y + bb.y;
    float o2 = (v.z - mean) * inv * gg.z + bb.z;
    float o3 = (v.w - mean) * inv * gg.w + bb.w;
    if (HOUT) {
        __half* oh = (__half*)outv;
        __half2 h01 = __floats2half2_rn(o0, o1);
        __half2 h23 = __floats2half2_rn(o2, o3);
        uint2 u; u.x = *(uint32_t*)&h01; u.y = *(uint32_t*)&h23;
        *(uint2*)(oh + (size_t)row * DM + tid * 4) = u;
    } else {
        float* of = (float*)outv;
        *(float4*)(of + (size_t)row * DM + tid * 4) = make_float4(o0, o1, o2, o3);
    }
}

// ---------------- launch -------------------------------------------------------
extern "C" void kernel_launch(void* const* d_in, const int* in_sizes, int n_in,
                              void* d_out, int out_size)
{
    const float* tgt    = (const float*)d_in[0];
    const float* memory = (const float*)d_in[1];

    const size_t OW = (size_t)LAYER * DM * DM;
    const size_t OB = (size_t)LAYER * DM;
    const float* sa_wq = (const float*)d_in[4]  + OW;
    const float* sa_wk = (const float*)d_in[5]  + OW;
    const float* sa_wv = (const float*)d_in[6]  + OW;
    const float* sa_wo = (const float*)d_in[7]  + OW;
    const float* sa_bq = (const float*)d_in[8]  + OB;
    const float* sa_bk = (const float*)d_in[9]  + OB;
    const float* sa_bv = (const float*)d_in[10] + OB;
    const float* sa_bo = (const float*)d_in[11] + OB;
    const float* ca_wq = (const float*)d_in[12] + OW;
    const float* ca_wk = (const float*)d_in[13] + OW;
    const float* ca_wv = (const float*)d_in[14] + OW;
    const float* ca_wo = (const float*)d_in[15] + OW;
    const float* ca_bq = (const float*)d_in[16] + OB;
    const float* ca_bk = (const float*)d_in[17] + OB;
    const float* ca_bv = (const float*)d_in[18] + OB;
    const float* ca_bo = (const float*)d_in[19] + OB;
    const float* ff_w1 = (const float*)d_in[20] + (size_t)LAYER * DM * FFD;
    const float* ff_b1 = (const float*)d_in[21] + (size_t)LAYER * FFD;
    const float* ff_w2 = (const float*)d_in[22] + (size_t)LAYER * FFD * DM;
    const float* ff_b2 = (const float*)d_in[23] + OB;
    const float* ln_g  = (const float*)d_in[24];
    const float* ln_b  = (const float*)d_in[25];

    __half *nh_, *qh_, *qkvh_, *kvh_, *vth_, *vth2_, *ath_, *ffh_, *memh_, *wth_, *w1th_, *w2th_;
    float *x_, *bc1_, *bc2_;
    cudaGetSymbolAddress((void**)&nh_,   g_nh);
    cudaGetSymbolAddress((void**)&qh_,   g_qh);
    cudaGetSymbolAddress((void**)&qkvh_, g_qkvh);
    cudaGetSymbolAddress((void**)&kvh_,  g_kvh);
    cudaGetSymbolAddress((void**)&vth_,  g_vth);
    cudaGetSymbolAddress((void**)&vth2_, g_vth2);
    cudaGetSymbolAddress((void**)&ath_,  g_ath);
    cudaGetSymbolAddress((void**)&ffh_,  g_ffh);
    cudaGetSymbolAddress((void**)&memh_, g_memh);
    cudaGetSymbolAddress((void**)&wth_,  g_wth);
    cudaGetSymbolAddress((void**)&w1th_, g_w1th);
    cudaGetSymbolAddress((void**)&w2th_, g_w2th);
    cudaGetSymbolAddress((void**)&x_,    g_x);
    cudaGetSymbolAddress((void**)&bc1_,  g_bc1);
    cudaGetSymbolAddress((void**)&bc2_,  g_bc2);

    static cudaStream_t s_aux = nullptr;
    static cudaEvent_t evF = nullptr, evP = nullptr, evR = nullptr, evKV = nullptr;
    if (!s_aux) {
        cudaStreamCreateWithFlags(&s_aux, cudaStreamNonBlocking);
        cudaEventCreateWithFlags(&evF,  cudaEventDisableTiming);
        cudaEventCreateWithFlags(&evP,  cudaEventDisableTiming);
        cudaEventCreateWithFlags(&evR,  cudaEventDisableTiming);
        cudaEventCreateWithFlags(&evKV, cudaEventDisableTiming);
    }

    const int S128 = 3 * (128 + 128) * 128;   // 98304
    const int S64  = 3 * (128 + 64)  * 128;   // 73728
    const int SFL8 = 65536;
    cudaFuncSetAttribute(mma_gemm<128,0,1,1>, cudaFuncAttributeMaxDynamicSharedMemorySize, S128);
    cudaFuncSetAttribute(mma_gemm<128,1,1,0>, cudaFuncAttributeMaxDynamicSharedMemorySize, S128);
    cudaFuncSetAttribute(mma_gemm<64,0,1,0>,  cudaFuncAttributeMaxDynamicSharedMemorySize, S64);
    cudaFuncSetAttribute(mma_gemm<64,2,0,0>,  cudaFuncAttributeMaxDynamicSharedMemorySize, S64);
    cudaFuncSetAttribute(flash_attn<1,8>,     cudaFuncAttributeMaxDynamicSharedMemorySize, SFL8);
    cudaFuncSetAttribute(flash_attn<0,8>,     cudaFuncAttributeMaxDynamicSharedMemorySize, SFL8);

    const int M = BB * TT;   // 4096

    __half* wqkvT = wth_ + 0 * DM * DM;
    __half* woT   = wth_ + 3 * DM * DM;
    __half* cqT   = wth_ + 4 * DM * DM;
    __half* ckvT  = wth_ + 5 * DM * DM;
    __half* coT   = wth_ + 7 * DM * DM;

    PrepArgs pa;
    pa.s8[0]=sa_wq; pa.d8[0]=wth_ + 0*DM*DM;
    pa.s8[1]=sa_wk; pa.d8[1]=wth_ + 1*DM*DM;
    pa.s8[2]=sa_wv; pa.d8[2]=wth_ + 2*DM*DM;
    pa.s8[3]=sa_wo; pa.d8[3]=woT;
    pa.s8[4]=ca_wq; pa.d8[4]=cqT;
    pa.s8[5]=ca_wk; pa.d8[5]=wth_ + 5*DM*DM;
    pa.s8[6]=ca_wv; pa.d8[6]=wth_ + 6*DM*DM;
    pa.s8[7]=ca_wo; pa.d8[7]=coT;
    pa.w1 = ff_w1; pa.w1t = w1th_;
    pa.w2 = ff_w2; pa.w2t = w2th_;
    pa.bq = sa_bq; pa.bk = sa_bk; pa.bv = sa_bv;
    pa.cbk = ca_bk; pa.cbv = ca_bv;
    pa.b1 = bc1_; pa.b2 = bc2_;
    pa.mem = memory; pa.memh = memh_;

    // ---- fork: SA-critical prep first, then rest + CA-KV on aux stream ----
    cudaEventRecord(evF, 0);
    cudaStreamWaitEvent(s_aux, evF, 0);
    prep_sa<<<769, dim3(32,8), 0, s_aux>>>(pa);
    cudaEventRecord(evP, s_aux);                       // SA weights + bc1 ready
    prep_rest<<<3329 + (BB*SS*DM)/2048, dim3(32,8), 0, s_aux>>>(pa);
    cudaEventRecord(evR, s_aux);                       // all other weights ready
    mma_gemm<128,0,1,1><<<dim3(8,64),256,S128,s_aux>>>(
        memh_,DM, ckvT,DM, bc2_,nullptr, kvh_,2*DM, DM, vth2_,512,BB*SS);
    cudaEventRecord(evKV, s_aux);                      // CA K/V ready

    // ---- main: self-attention: x = tgt + SA(LN(tgt)) ----
    ln_kernel<1><<<M, 128>>>(tgt, ln_g, ln_b, nh_);
    cudaStreamWaitEvent(0, evP, 0);
    mma_gemm<128,0,1,1><<<dim3(12,32),256,S128>>>(
        nh_,DM, wqkvT,DM, bc1_,nullptr, qkvh_,3*DM, DM, vth_,1024,M);
    flash_attn<1,8><<<dim3(4,64),256,SFL8>>>(qkvh_,3*DM, qkvh_+DM,3*DM, vth_, ath_, TT);
    cudaStreamWaitEvent(0, evR, 0);
    mma_gemm<64,2,0,0><<<dim3(8,32),256,S64>>>(
        ath_,DM, woT,DM, sa_bo,tgt, x_,DM, DM, nullptr,0,0);

    // ---- cross-attention: x += CA(LN(x), memory) ----
    ln_kernel<1><<<M, 128>>>(x_, ln_g, ln_b, nh_);
    mma_gemm<64,0,1,0><<<dim3(8,32),256,S64>>>(
        nh_,DM, cqT,DM, ca_bq,nullptr, qh_,DM, DM, nullptr,0,0);
    cudaStreamWaitEvent(0, evKV, 0);
    flash_attn<0,8><<<dim3(4,64),256,SFL8>>>(qh_,DM, kvh_,2*DM, vth2_, ath_, SS);
    mma_gemm<64,2,0,0><<<dim3(8,32),256,S64>>>(
        ath_,DM, coT,DM, ca_bo,x_, x_,DM, DM, nullptr,0,0);

    // ---- FFN: x += W2 relu(W1 LN(x)) ----
    ln_kernel<1><<<M, 128>>>(x_, ln_g, ln_b, nh_);
    mma_gemm<128,1,1,0><<<dim3(16,32),256,S128>>>(
        nh_,DM,  w1th_,DM,  ff_b1,nullptr, ffh_,FFD, DM, nullptr,0,0);
    mma_gemm<64,2,0,0><<<dim3(8,32),256,S64>>>(
        ffh_,FFD, w2th_,FFD, ff_b2,x_, x_,DM, FFD, nullptr,0,0);

    // ---- final LN -> out ----
    ln_kernel<0><<<M, 128>>>(x_, ln_g, ln_b, (float*)d_out);
}

// round 16
// speedup vs baseline: 1.2763x; 1.2763x over previous
#include <cuda_runtime.h>
#include <cuda_fp16.h>
#include <cstdint>

// Problem constants
#define NH   8
#define DM   512
#define FFD  2048
#define BB   8
#define TT   512
#define SS   1024
#define LAYER 5

// ---------------- scratch (device globals) ------------------------------------
__device__ __half g_nh  [BB*TT*DM];
__device__ __half g_qh  [BB*TT*DM];
__device__ __half g_qkvh[BB*TT*3*DM];
__device__ __half g_kvh [BB*SS*2*DM];
__device__ __half g_vth [DM*BB*TT];
__device__ __half g_vth2[DM*BB*SS];
__device__ __half g_ath [BB*TT*DM];
__device__ __half g_ffh [BB*TT*FFD];
__device__ __half g_memh[BB*SS*DM];
__device__ __half g_wth [8*DM*DM];
__device__ __half g_w1th[FFD*DM];
__device__ __half g_w2th[DM*FFD];
__device__ float  g_x   [BB*TT*DM];
__device__ float  g_bc1 [3*DM];
__device__ float  g_bc2 [2*DM];

// ---------------- helpers ------------------------------------------------------
__device__ __forceinline__ uint32_t smem_u32(const void* p) {
    uint32_t a;
    asm("{ .reg .u64 t; cvta.to.shared.u64 t, %1; cvt.u32.u64 %0, t; }" : "=r"(a) : "l"(p));
    return a;
}
__device__ __forceinline__ uint32_t h2u(__half2 h) { return *(uint32_t*)&h; }

#define CP16(dst, src) \
    asm volatile("cp.async.cg.shared.global [%0], [%1], 16;" :: "r"(dst), "l"(src))
#define CP_COMMIT() asm volatile("cp.async.commit_group;" ::: "memory")
#define CP_WAIT1()  asm volatile("cp.async.wait_group 1;" ::: "memory")
#define CP_WAIT0()  asm volatile("cp.async.wait_group 0;" ::: "memory")

#define MMA_F16(c, a, b) \
    asm volatile("mma.sync.aligned.m16n8k16.row.col.f32.f16.f16.f32 " \
        "{%0,%1,%2,%3}, {%4,%5,%6,%7}, {%8,%9}, {%0,%1,%2,%3};" \
        : "+f"((c)[0]), "+f"((c)[1]), "+f"((c)[2]), "+f"((c)[3]) \
        : "r"((a)[0]), "r"((a)[1]), "r"((a)[2]), "r"((a)[3]), "r"((b)[0]), "r"((b)[1]))

#define LDSM4(d0, d1, d2, d3, addr) \
    asm volatile("ldmatrix.sync.aligned.m8n8.x4.shared.b16 {%0,%1,%2,%3}, [%4];" \
        : "=r"(d0), "=r"(d1), "=r"(d2), "=r"(d3) : "r"(addr))

// ============ mma.sync fp16 GEMM, 3-stage pipeline, ldmatrix fragments =========
template<int BN, int EPI, int HOUT, int VT>
__global__ __launch_bounds__(256) void mma_gemm(
    const __half* __restrict__ A, int lda,
    const __half* __restrict__ B, int ldb,
    const float* __restrict__ bias, const float* __restrict__ res,
    void* __restrict__ Cv, int ldc, int K,
    __half* __restrict__ vtp, int vtn0, int vtld)
{
    constexpr int WTM = (BN == 128) ? 64 : 32;
    constexpr int MW  = 128 / WTM;
    constexpr int MF  = WTM / 16;
    constexpr int NF  = 4;
    constexpr int SSZB = (128 + BN) * 128;

    const int m0 = blockIdx.y * 128;
    const int n0 = blockIdx.x * BN;

    extern __shared__ char smem[];
    const uint32_t uS = smem_u32(smem);

    const int tid  = threadIdx.x;
    const int lane = tid & 31;
    const int wid  = tid >> 5;
    const int wm   = wid & (MW - 1);
    const int wn   = wid / MW;
    const int laneR = lane >> 2, laneC = lane & 3;

    const int mat = lane >> 3, mrr = lane & 7;
    const int ag_hi = mat >> 1;
    const int bg_lo = mat & 1;
    int aro[MF], arx[MF];
#pragma unroll
    for (int mf = 0; mf < MF; mf++) {
        int r = wm * WTM + mf * 16 + ((mat & 1) << 3) + mrr;
        aro[mf] = r * 128; arx[mf] = r & 7;
    }
    int bro[NF / 2], brx[NF / 2];
#pragma unroll
    for (int p = 0; p < NF / 2; p++) {
        int r = wn * 32 + (2 * p + (mat >> 1)) * 8 + mrr;
        bro[p] = r * 128; brx[p] = r & 7;
    }

    const int nch = K >> 6;

    auto load_chunk = [&](int c) {
        const int st = c % 3;
        const uint32_t ua = uS + st * SSZB;
        const uint32_t ub = ua + 128 * 128;
        const int k0 = c << 6;
#pragma unroll
        for (int i = 0; i < 4; i++) {
            int idx = tid + i * 256; int r = idx >> 3, f = idx & 7;
            CP16(ua + r * 128 + ((f ^ (r & 7)) << 4),
                 A + (size_t)(m0 + r) * lda + k0 + f * 8);
        }
#pragma unroll
        for (int i = 0; i < BN / 32; i++) {
            int idx = tid + i * 256; int r = idx >> 3, f = idx & 7;
            CP16(ub + r * 128 + ((f ^ (r & 7)) << 4),
                 B + (size_t)(n0 + r) * ldb + k0 + f * 8);
        }
        CP_COMMIT();
    };

    float acc[MF][NF][4] = {};

    load_chunk(0);
    load_chunk(1);
    for (int c = 0; c < nch; c++) {
        if (c + 1 < nch) CP_WAIT1(); else CP_WAIT0();
        __syncthreads();
        if (c + 2 < nch) load_chunk(c + 2);
        const int st = c % 3;
        const uint32_t uA_s = uS + st * SSZB;
        const uint32_t uB_s = uA_s + 128 * 128;
#pragma unroll
        for (int ks = 0; ks < 4; ks++) {
            const int gA = 2 * ks + ag_hi;
            const int gB = 2 * ks + bg_lo;
            uint32_t af[MF][4];
#pragma unroll
            for (int mf = 0; mf < MF; mf++)
                LDSM4(af[mf][0], af[mf][1], af[mf][2], af[mf][3],
                      uA_s + aro[mf] + ((gA ^ arx[mf]) << 4));
            uint32_t bf[NF][2];
#pragma unroll
            for (int p = 0; p < NF / 2; p++)
                LDSM4(bf[2*p][0], bf[2*p][1], bf[2*p+1][0], bf[2*p+1][1],
                      uB_s + bro[p] + ((gB ^ brx[p]) << 4));
#pragma unroll
            for (int mf = 0; mf < MF; mf++)
#pragma unroll
                for (int nf = 0; nf < NF; nf++)
                    MMA_F16(acc[mf][nf], af[mf], bf[nf]);
        }
    }

    const bool isv = VT && (n0 >= vtn0);
#pragma unroll
    for (int mf = 0; mf < MF; mf++) {
#pragma unroll
        for (int nf = 0; nf < NF; nf++) {
            int r  = m0 + wm * WTM + mf * 16 + laneR;
            int cc = n0 + wn * 32 + nf * 8 + laneC * 2;
            float v0 = acc[mf][nf][0], v1 = acc[mf][nf][1];
            float v2 = acc[mf][nf][2], v3 = acc[mf][nf][3];
            float2 bb = *(const float2*)(bias + cc);
            v0 += bb.x; v1 += bb.y; v2 += bb.x; v3 += bb.y;
            if (EPI == 1) {
                v0 = fmaxf(v0, 0.f); v1 = fmaxf(v1, 0.f);
                v2 = fmaxf(v2, 0.f); v3 = fmaxf(v3, 0.f);
            }
            if (EPI == 2) {
                float2 r0 = *(const float2*)(res + (size_t)r * ldc + cc);
                float2 r1 = *(const float2*)(res + (size_t)(r + 8) * ldc + cc);
                v0 += r0.x; v1 += r0.y; v2 += r1.x; v3 += r1.y;
            }
            if (isv) {
                __half* c0 = vtp + (size_t)(cc     - vtn0) * vtld;
                __half* c1 = vtp + (size_t)(cc + 1 - vtn0) * vtld;
                c0[r] = __float2half(v0); c1[r] = __float2half(v1);
                c0[r + 8] = __float2half(v2); c1[r + 8] = __float2half(v3);
            } else if (HOUT) {
                __half* Ch = (__half*)Cv;
                *(__half2*)(Ch + (size_t)r * ldc + cc)       = __floats2half2_rn(v0, v1);
                *(__half2*)(Ch + (size_t)(r + 8) * ldc + cc) = __floats2half2_rn(v2, v3);
            } else {
                float* Cf = (float*)Cv;
                *(float2*)(Cf + (size_t)r * ldc + cc)       = make_float2(v0, v1);
                *(float2*)(Cf + (size_t)(r + 8) * ldc + cc) = make_float2(v2, v3);
            }
        }
    }
}

// ============ fused flash attention (fp16, 3-stage KV ring, P in registers) ====
// smem: Q 16K | K 3x8K | V 3x8K  = 64 KB. 2 CTA/SM.
template<int CAUSAL>
__global__ __launch_bounds__(256, 2) void flash_attn(
    const __half* __restrict__ Q, int ldq,
    const __half* __restrict__ Kg, int ldk,
    const __half* __restrict__ Vt, __half* __restrict__ O, int Slen)
{
    extern __shared__ char sm[];
    const uint32_t uQ = smem_u32(sm);
    const uint32_t uK = uQ + 16384;
    const uint32_t uV = uK + 24576;

    const int mt = blockIdx.x, bh = blockIdx.y;
    const int b = bh >> 3, h = bh & 7;
    const int m0 = mt * 128;
    const int tid = threadIdx.x, lane = tid & 31, wid = tid >> 5;
    const int laneR = lane >> 2, laneC = lane & 3;

    const __half* Qp = Q + ((size_t)b * TT + m0) * ldq + h * 64;
    const __half* Kp = Kg + (size_t)b * Slen * ldk + h * 64;
    const __half* Vp = Vt + (size_t)(h * 64) * (BB * Slen) + (size_t)b * Slen;
    __half* Op = O + ((size_t)b * TT + m0) * DM + h * 64;

    const int wr0 = wid * 16;

    const int mat = lane >> 3, mrr = lane & 7;
    const int ag_hi = mat >> 1;
    const int bg_lo = mat & 1;
    const int qrow = wr0 + ((mat & 1) << 3) + mrr;
    const int qro = qrow * 128, qrx = qrow & 7;
    int bro[4], brx[4];
#pragma unroll
    for (int p = 0; p < 4; p++) {
        int r = p * 16 + ((mat >> 1) << 3) + mrr;
        bro[p] = r * 128; brx[p] = r & 7;
    }

#pragma unroll
    for (int i = 0; i < 4; i++) {
        int idx = tid + i * 256;
        int r = idx >> 3, f = idx & 7;
        CP16(uQ + r * 128 + ((f ^ (r & 7)) << 4), Qp + (size_t)r * ldq + f * 8);
    }

    auto load_kv = [&](int c) {
        const int st = c % 3;
        const int s0 = c * 64;
#pragma unroll
        for (int i = 0; i < 2; i++) {
            int idx = tid + i * 256;
            int r = idx >> 3, f = idx & 7;
            CP16(uK + st * 8192 + r * 128 + ((f ^ (r & 7)) << 4),
                 Kp + (size_t)(s0 + r) * ldk + f * 8);
        }
#pragma unroll
        for (int i = 0; i < 2; i++) {
            int idx = tid + i * 256;
            int r = idx >> 3, f = idx & 7;
            CP16(uV + st * 8192 + r * 128 + ((f ^ (r & 7)) << 4),
                 Vp + (size_t)r * (BB * Slen) + s0 + f * 8);
        }
        CP_COMMIT();
    };

    const int nch = CAUSAL ? (m0 + 128) / 64 : Slen / 64;
    float mr0 = -1e30f, mr1 = -1e30f, l0 = 0.f, l1 = 0.f;
    float oacc[8][4] = {};

    load_kv(0);
    load_kv(1);
    for (int c = 0; c < nch; c++) {
        if (c + 1 < nch) CP_WAIT1(); else CP_WAIT0();
        __syncthreads();
        if (c + 2 < nch) load_kv(c + 2);
        const int s0 = c * 64;
        const bool active = !CAUSAL || (s0 <= m0 + wr0 + 15);
        if (active) {
            const uint32_t uKb = uK + (c % 3) * 8192;
            const uint32_t uVb = uV + (c % 3) * 8192;

            float sacc[8][4] = {};
#pragma unroll
            for (int ks = 0; ks < 4; ks++) {
                const int gA = 2 * ks + ag_hi;
                const int gB = 2 * ks + bg_lo;
                uint32_t af[4];
                LDSM4(af[0], af[1], af[2], af[3], uQ + qro + ((gA ^ qrx) << 4));
                uint32_t bf[8][2];
#pragma unroll
                for (int p = 0; p < 4; p++)
                    LDSM4(bf[2*p][0], bf[2*p][1], bf[2*p+1][0], bf[2*p+1][1],
                          uKb + bro[p] + ((gB ^ brx[p]) << 4));
#pragma unroll
                for (int nf = 0; nf < 8; nf++)
                    MMA_F16(sacc[nf], af, bf[nf]);
            }

            const float SCL = 0.125f;
            const int t0g = m0 + wr0 + laneR;
            float rmax0 = -1e30f, rmax1 = -1e30f;
#pragma unroll
            for (int nf = 0; nf < 8; nf++) {
                int sg = s0 + nf * 8 + 2 * laneC;
                float v0 = sacc[nf][0] * SCL, v1 = sacc[nf][1] * SCL;
                float v2 = sacc[nf][2] * SCL, v3 = sacc[nf][3] * SCL;
                if (CAUSAL) {
                    if (sg     > t0g)     v0 = -1e30f;
                    if (sg + 1 > t0g)     v1 = -1e30f;
                    if (sg     > t0g + 8) v2 = -1e30f;
                    if (sg + 1 > t0g + 8) v3 = -1e30f;
                }
                sacc[nf][0] = v0; sacc[nf][1] = v1;
                sacc[nf][2] = v2; sacc[nf][3] = v3;
                rmax0 = fmaxf(rmax0, fmaxf(v0, v1));
                rmax1 = fmaxf(rmax1, fmaxf(v2, v3));
            }
            rmax0 = fmaxf(rmax0, __shfl_xor_sync(0xffffffffu, rmax0, 1));
            rmax0 = fmaxf(rmax0, __shfl_xor_sync(0xffffffffu, rmax0, 2));
            rmax1 = fmaxf(rmax1, __shfl_xor_sync(0xffffffffu, rmax1, 1));
            rmax1 = fmaxf(rmax1, __shfl_xor_sync(0xffffffffu, rmax1, 2));
            float mn0 = fmaxf(mr0, rmax0), mn1 = fmaxf(mr1, rmax1);
            float al0 = __expf(mr0 - mn0), al1 = __expf(mr1 - mn1);
            mr0 = mn0; mr1 = mn1;

            uint32_t ph[8][2];
            float rs0 = 0.f, rs1 = 0.f;
#pragma unroll
            for (int nf = 0; nf < 8; nf++) {
                float e0 = __expf(sacc[nf][0] - mn0);
                float e1 = __expf(sacc[nf][1] - mn0);
                float e2 = __expf(sacc[nf][2] - mn1);
                float e3 = __expf(sacc[nf][3] - mn1);
                rs0 += e0 + e1; rs1 += e2 + e3;
                ph[nf][0] = h2u(__floats2half2_rn(e0, e1));
                ph[nf][1] = h2u(__floats2half2_rn(e2, e3));
            }
            rs0 += __shfl_xor_sync(0xffffffffu, rs0, 1);
            rs0 += __shfl_xor_sync(0xffffffffu, rs0, 2);
            rs1 += __shfl_xor_sync(0xffffffffu, rs1, 1);
            rs1 += __shfl_xor_sync(0xffffffffu, rs1, 2);
            l0 = l0 * al0 + rs0;
            l1 = l1 * al1 + rs1;
#pragma unroll
            for (int nf = 0; nf < 8; nf++) {
                oacc[nf][0] *= al0; oacc[nf][1] *= al0;
                oacc[nf][2] *= al1; oacc[nf][3] *= al1;
            }

#pragma unroll
            for (int j = 0; j < 4; j++) {
                const int gB = 2 * j + bg_lo;
                uint32_t af[4] = { ph[2*j][0], ph[2*j][1], ph[2*j+1][0], ph[2*j+1][1] };
#pragma unroll
                for (int p = 0; p < 4; p++) {
                    uint32_t bf0[2], bf1[2];
                    LDSM4(bf0[0], bf0[1], bf1[0], bf1[1],
                          uVb + bro[p] + ((gB ^ brx[p]) << 4));
                    MMA_F16(oacc[2*p],     af, bf0);
                    MMA_F16(oacc[2*p + 1], af, bf1);
                }
            }
        }
    }

    const float inv0 = 1.f / l0, inv1 = 1.f / l1;
#pragma unroll
    for (int nf = 0; nf < 8; nf++) {
        int cc = nf * 8 + 2 * laneC;
        int r = wr0 + laneR;
        *(__half2*)(Op + (size_t)r * DM + cc) =
            __floats2half2_rn(oacc[nf][0] * inv0, oacc[nf][1] * inv0);
        *(__half2*)(Op + (size_t)(r + 8) * DM + cc) =
            __floats2half2_rn(oacc[nf][2] * inv1, oacc[nf][3] * inv1);
    }
}

// ---------------- prep: transposes->half + bias concats + memory->half ---------
struct PrepArgs {
    const float* s8[8]; __half* d8[8];
    const float* w1; __half* w1t;
    const float* w2; __half* w2t;
    const float* bq; const float* bk; const float* bv;
    const float* cbk; const float* cbv;
    float* b1; float* b2;
    const float* mem; __half* memh;
};
__global__ __launch_bounds__(256) void prep_all(PrepArgs p)
{
    __shared__ float t[32][33];
    const int idx = blockIdx.x;
    const int tx = threadIdx.x, ty = threadIdx.y;

    if (idx >= 4097) {   // memory fp32 -> half
        int j = idx - 4097;
        int base = j * 2048 + (ty * 32 + tx) * 8;
        float4 a = *(const float4*)(p.mem + base);
        float4 b = *(const float4*)(p.mem + base + 4);
        __half2 h0 = __floats2half2_rn(a.x, a.y);
        __half2 h1 = __floats2half2_rn(a.z, a.w);
        __half2 h2 = __floats2half2_rn(b.x, b.y);
        __half2 h3 = __floats2half2_rn(b.z, b.w);
        uint4 o;
        o.x = *(uint32_t*)&h0; o.y = *(uint32_t*)&h1;
        o.z = *(uint32_t*)&h2; o.w = *(uint32_t*)&h3;
        *(uint4*)(p.memh + base) = o;
        return;
    }

    const float* src; __half* dst; int R, C, bx, by;
    if (idx < 2048) {
        int m = idx >> 8, tt = idx & 255;
        src = p.s8[m]; dst = p.d8[m]; R = 512; C = 512;
        bx = tt & 15; by = tt >> 4;
    } else if (idx < 3072) {
        int tt = idx - 2048;
        src = p.w1; dst = p.w1t; R = 512; C = 2048;
        bx = tt & 63; by = tt >> 6;
    } else if (idx < 4096) {
        int tt = idx - 3072;
        src = p.w2; dst = p.w2t; R = 2048; C = 512;
        bx = tt & 15; by = tt >> 4;
    } else {
        int i = ty * 32 + tx;
#pragma unroll
        for (int j = 0; j < 2; j++) {
            int c = i + j * 256;
            p.b1[c] = p.bq[c]; p.b1[512 + c] = p.bk[c]; p.b1[1024 + c] = p.bv[c];
            p.b2[c] = p.cbk[c]; p.b2[512 + c] = p.cbv[c];
        }
        return;
    }
    int x = bx * 32 + tx, y = by * 32;
#pragma unroll
    for (int i = 0; i < 4; i++)
        t[ty + i * 8][tx] = src[(size_t)(y + ty + i * 8) * C + x];
    __syncthreads();
    int x2 = by * 32 + tx, y2 = bx * 32;
#pragma unroll
    for (int i = 0; i < 4; i++)
        dst[(size_t)(y2 + ty + i * 8) * R + x2] = __float2half(t[tx][ty + i * 8]);
}

// ---------------- LayerNorm: warp-per-row, shuffle-only reduction ---------------
template<int HOUT>
__global__ __launch_bounds__(128) void ln_kernel(
    const float* __restrict__ x, const float* __restrict__ g,
    const float* __restrict__ b, void* __restrict__ outv)
{
    const int wid = threadIdx.x >> 5, lane = threadIdx.x & 31;
    const int row = blockIdx.x * 4 + wid;
    const float* xr = x + (size_t)row * DM;

    float4 v[4];
    float s = 0.f, s2 = 0.f;
#pragma unroll
    for (int i = 0; i < 4; i++) {
        v[i] = *(const float4*)(xr + (lane + i * 32) * 4);
        s  += v[i].x + v[i].y + v[i].z + v[i].w;
        s2 += v[i].x * v[i].x + v[i].y * v[i].y + v[i].z * v[i].z + v[i].w * v[i].w;
    }
#pragma unroll
    for (int o = 16; o; o >>= 1) {
        s  += __shfl_xor_sync(0xffffffffu, s,  o);
        s2 += __shfl_xor_sync(0xffffffffu, s2, o);
    }
    const float mean = s * (1.0f / DM);
    const float var  = s2 * (1.0f / DM) - mean * mean;
    const float inv  = rsqrtf(var + 1e-5f);

#pragma unroll
    for (int i = 0; i < 4; i++) {
        const int col = (lane + i * 32) * 4;
        float4 gg = *(const float4*)(g + col);
        float4 bb = *(const float4*)(b + col);
        float o0 = (v[i].x - mean) * inv * gg.x + bb.x;
        float o1 = (v[i].y - mean) * inv * gg.y + bb.y;
        float o2 = (v[i].z - mean) * inv * gg.z + bb.z;
        float o3 = (v[i].w - mean) * inv * gg.w + bb.w;
        if (HOUT) {
            __half* oh = (__half*)outv;
            __half2 h01 = __floats2half2_rn(o0, o1);
            __half2 h23 = __floats2half2_rn(o2, o3);
            uint2 u; u.x = *(uint32_t*)&h01; u.y = *(uint32_t*)&h23;
            *(uint2*)(oh + (size_t)row * DM + col) = u;
        } else {
            float* of = (float*)outv;
            *(float4*)(of + (size_t)row * DM + col) = make_float4(o0, o1, o2, o3);
        }
    }
}

// ---------------- launch -------------------------------------------------------
extern "C" void kernel_launch(void* const* d_in, const int* in_sizes, int n_in,
                              void* d_out, int out_size)
{
    const float* tgt    = (const float*)d_in[0];
    const float* memory = (const float*)d_in[1];

    const size_t OW = (size_t)LAYER * DM * DM;
    const size_t OB = (size_t)LAYER * DM;
    const float* sa_wq = (const float*)d_in[4]  + OW;
    const float* sa_wk = (const float*)d_in[5]  + OW;
    const float* sa_wv = (const float*)d_in[6]  + OW;
    const float* sa_wo = (const float*)d_in[7]  + OW;
    const float* sa_bq = (const float*)d_in[8]  + OB;
    const float* sa_bk = (const float*)d_in[9]  + OB;
    const float* sa_bv = (const float*)d_in[10] + OB;
    const float* sa_bo = (const float*)d_in[11] + OB;
    const float* ca_wq = (const float*)d_in[12] + OW;
    const float* ca_wk = (const float*)d_in[13] + OW;
    const float* ca_wv = (const float*)d_in[14] + OW;
    const float* ca_wo = (const float*)d_in[15] + OW;
    const float* ca_bq = (const float*)d_in[16] + OB;
    const float* ca_bk = (const float*)d_in[17] + OB;
    const float* ca_bv = (const float*)d_in[18] + OB;
    const float* ca_bo = (const float*)d_in[19] + OB;
    const float* ff_w1 = (const float*)d_in[20] + (size_t)LAYER * DM * FFD;
    const float* ff_b1 = (const float*)d_in[21] + (size_t)LAYER * FFD;
    const float* ff_w2 = (const float*)d_in[22] + (size_t)LAYER * FFD * DM;
    const float* ff_b2 = (const float*)d_in[23] + OB;
    const float* ln_g  = (const float*)d_in[24];
    const float* ln_b  = (const float*)d_in[25];

    __half *nh_, *qh_, *qkvh_, *kvh_, *vth_, *vth2_, *ath_, *ffh_, *memh_, *wth_, *w1th_, *w2th_;
    float *x_, *bc1_, *bc2_;
    cudaGetSymbolAddress((void**)&nh_,   g_nh);
    cudaGetSymbolAddress((void**)&qh_,   g_qh);
    cudaGetSymbolAddress((void**)&qkvh_, g_qkvh);
    cudaGetSymbolAddress((void**)&kvh_,  g_kvh);
    cudaGetSymbolAddress((void**)&vth_,  g_vth);
    cudaGetSymbolAddress((void**)&vth2_, g_vth2);
    cudaGetSymbolAddress((void**)&ath_,  g_ath);
    cudaGetSymbolAddress((void**)&ffh_,  g_ffh);
    cudaGetSymbolAddress((void**)&memh_, g_memh);
    cudaGetSymbolAddress((void**)&wth_,  g_wth);
    cudaGetSymbolAddress((void**)&w1th_, g_w1th);
    cudaGetSymbolAddress((void**)&w2th_, g_w2th);
    cudaGetSymbolAddress((void**)&x_,    g_x);
    cudaGetSymbolAddress((void**)&bc1_,  g_bc1);
    cudaGetSymbolAddress((void**)&bc2_,  g_bc2);

    static cudaStream_t s_aux = nullptr;
    static cudaEvent_t evF = nullptr, evP = nullptr, evKV = nullptr;
    if (!s_aux) {
        cudaStreamCreateWithFlags(&s_aux, cudaStreamNonBlocking);
        cudaEventCreateWithFlags(&evF,  cudaEventDisableTiming);
        cudaEventCreateWithFlags(&evP,  cudaEventDisableTiming);
        cudaEventCreateWithFlags(&evKV, cudaEventDisableTiming);
    }

    const int S128 = 3 * (128 + 128) * 128;   // 98304
    const int S64  = 3 * (128 + 64)  * 128;   // 73728
    const int SFL  = 65536;
    cudaFuncSetAttribute(mma_gemm<128,0,1,1>, cudaFuncAttributeMaxDynamicSharedMemorySize, S128);
    cudaFuncSetAttribute(mma_gemm<128,1,1,0>, cudaFuncAttributeMaxDynamicSharedMemorySize, S128);
    cudaFuncSetAttribute(mma_gemm<64,0,1,0>,  cudaFuncAttributeMaxDynamicSharedMemorySize, S64);
    cudaFuncSetAttribute(mma_gemm<64,2,0,0>,  cudaFuncAttributeMaxDynamicSharedMemorySize, S64);
    cudaFuncSetAttribute(flash_attn<1>,       cudaFuncAttributeMaxDynamicSharedMemorySize, SFL);
    cudaFuncSetAttribute(flash_attn<0>,       cudaFuncAttributeMaxDynamicSharedMemorySize, SFL);

    const int M = BB * TT;   // 4096

    __half* wqkvT = wth_ + 0 * DM * DM;
    __half* woT   = wth_ + 3 * DM * DM;
    __half* cqT   = wth_ + 4 * DM * DM;
    __half* ckvT  = wth_ + 5 * DM * DM;
    __half* coT   = wth_ + 7 * DM * DM;

    PrepArgs pa;
    pa.s8[0]=sa_wq; pa.d8[0]=wth_ + 0*DM*DM;
    pa.s8[1]=sa_wk; pa.d8[1]=wth_ + 1*DM*DM;
    pa.s8[2]=sa_wv; pa.d8[2]=wth_ + 2*DM*DM;
    pa.s8[3]=sa_wo; pa.d8[3]=woT;
    pa.s8[4]=ca_wq; pa.d8[4]=cqT;
    pa.s8[5]=ca_wk; pa.d8[5]=wth_ + 5*DM*DM;
    pa.s8[6]=ca_wv; pa.d8[6]=wth_ + 6*DM*DM;
    pa.s8[7]=ca_wo; pa.d8[7]=coT;
    pa.w1 = ff_w1; pa.w1t = w1th_;
    pa.w2 = ff_w2; pa.w2t = w2th_;
    pa.bq = sa_bq; pa.bk = sa_bk; pa.bv = sa_bv;
    pa.cbk = ca_bk; pa.cbv = ca_bv;
    pa.b1 = bc1_; pa.b2 = bc2_;
    pa.mem = memory; pa.memh = memh_;

    // ---- fork: prep + CA-KV projection on aux stream (R12 structure) ----
    cudaEventRecord(evF, 0);
    cudaStreamWaitEvent(s_aux, evF, 0);
    prep_all<<<4097 + (BB*SS*DM)/2048, dim3(32,8), 0, s_aux>>>(pa);
    cudaEventRecord(evP, s_aux);
    mma_gemm<128,0,1,1><<<dim3(8,64),256,S128,s_aux>>>(
        memh_,DM, ckvT,DM, bc2_,nullptr, kvh_,2*DM, DM, vth2_,512,BB*SS);
    cudaEventRecord(evKV, s_aux);

    // ---- main: self-attention: x = tgt + SA(LN(tgt)) ----
    ln_kernel<1><<<M/4, 128>>>(tgt, ln_g, ln_b, nh_);
    cudaStreamWaitEvent(0, evP, 0);
    mma_gemm<128,0,1,1><<<dim3(12,32),256,S128>>>(
        nh_,DM, wqkvT,DM, bc1_,nullptr, qkvh_,3*DM, DM, vth_,1024,M);
    flash_attn<1><<<dim3(4,64),256,SFL>>>(qkvh_,3*DM, qkvh_+DM,3*DM, vth_, ath_, TT);
    mma_gemm<64,2,0,0><<<dim3(8,32),256,S64>>>(
        ath_,DM, woT,DM, sa_bo,tgt, x_,DM, DM, nullptr,0,0);

    // ---- cross-attention: x += CA(LN(x), memory) ----
    ln_kernel<1><<<M/4, 128>>>(x_, ln_g, ln_b, nh_);
    mma_gemm<64,0,1,0><<<dim3(8,32),256,S64>>>(
        nh_,DM, cqT,DM, ca_bq,nullptr, qh_,DM, DM, nullptr,0,0);
    cudaStreamWaitEvent(0, evKV, 0);
    flash_attn<0><<<dim3(4,64),256,SFL>>>(qh_,DM, kvh_,2*DM, vth2_, ath_, SS);
    mma_gemm<64,2,0,0><<<dim3(8,32),256,S64>>>(
        ath_,DM, coT,DM, ca_bo,x_, x_,DM, DM, nullptr,0,0);

    // ---- FFN: x += W2 relu(W1 LN(x)) ----
    ln_kernel<1><<<M/4, 128>>>(x_, ln_g, ln_b, nh_);
    mma_gemm<128,1,1,0><<<dim3(16,32),256,S128>>>(
        nh_,DM,  w1th_,DM,  ff_b1,nullptr, ffh_,FFD, DM, nullptr,0,0);
    mma_gemm<64,2,0,0><<<dim3(8,32),256,S64>>>(
        ffh_,FFD, w2th_,FFD, ff_b2,x_, x_,DM, FFD, nullptr,0,0);

    // ---- final LN -> out ----
    ln_kernel<0><<<M/4, 128>>>(x_, ln_g, ln_b, (float*)d_out);
}